// round 9
// baseline (speedup 1.0000x reference)
#include <cuda_runtime.h>

static constexpr int C = 512;
static constexpr int B = 8;
static constexpr int L = 4096;
static constexpr int TOPK = 256;          // C * (1 - EXCHANGE_RATIO)

// Per-array tables (written by blocks 0/1):
//   g_tp[a][c] = -1 if channel c is in top-k of |bn_a|, else its position in
//                the ascending-index list of non-top channels (0..255).
//   g_nt[a][k] = k-th non-top channel of array a (ascending index order).
__device__ int g_tp[2][C];
__device__ int g_nt[2][TOPK];
// Handshake state (zero-initialized; reset by the last block each run).
__device__ int g_ready;
__device__ int g_done;

struct U64x4 { unsigned long long a, b, c, d; };

// 256-bit read-only load with L2 evict-last: inputs are re-read every graph
// replay and never written — keep them resident in the ~126 MB L2.
// (ptxas on sm_103a only accepts .L2::evict_last with .v8.b32/.v4.b64.)
__device__ __forceinline__ U64x4 ld32_evict_last(const void* p) {
    U64x4 v;
    asm volatile("ld.global.nc.L2::evict_last.v4.b64 {%0,%1,%2,%3}, [%4];"
                 : "=l"(v.a), "=l"(v.b), "=l"(v.c), "=l"(v.d) : "l"(p));
    return v;
}

__device__ __forceinline__ float4 f4_lo(const U64x4& v) {
    float4 r;
    r.x = __uint_as_float((unsigned)(v.a));
    r.y = __uint_as_float((unsigned)(v.a >> 32));
    r.z = __uint_as_float((unsigned)(v.b));
    r.w = __uint_as_float((unsigned)(v.b >> 32));
    return r;
}
__device__ __forceinline__ float4 f4_hi(const U64x4& v) {
    float4 r;
    r.x = __uint_as_float((unsigned)(v.c));
    r.y = __uint_as_float((unsigned)(v.c >> 32));
    r.z = __uint_as_float((unsigned)(v.d));
    r.w = __uint_as_float((unsigned)(v.d >> 32));
    return r;
}

__global__ void __launch_bounds__(256)
exchange_fused_kernel(const float4* __restrict__ x1,
                      const float4* __restrict__ x2,
                      float4* __restrict__ out,
                      const float* __restrict__ bn1,
                      const float* __restrict__ bn2) {
    unsigned row = blockIdx.x;             // INPUT row: a*4096 + b*512 + c
    int t = threadIdx.x;

    // ─── Phase 1: blocks 0 and 1 build the map for bn1 / bn2 ───
    if (row < 2) {
        __shared__ unsigned long long key[C];
        __shared__ unsigned ballots[16];

        int a = row;
        const float* bn = a ? bn2 : bn1;

        // Non-negative floats order like their bit patterns.
        // key = (bits << 10) | (1023 - c): equal values -> smaller index
        // ranks higher, matching jax.lax.top_k tie semantics.
        {
            unsigned b0 = __float_as_uint(fabsf(bn[t]));
            unsigned b1 = __float_as_uint(fabsf(bn[t + 256]));
            key[t]       = ((unsigned long long)b0 << 10) | (unsigned)(1023 - t);
            key[t + 256] = ((unsigned long long)b1 << 10) | (unsigned)(1023 - (t + 256));
        }
        __syncthreads();

        // Each thread ranks two channels; one LDS.128/iter serves both.
        unsigned long long k0 = key[t], k1 = key[t + 256];
        int r0 = 0, r1 = 0;
        const ulonglong2* k2 = (const ulonglong2*)key;
        #pragma unroll 8
        for (int j = 0; j < C / 2; ++j) {
            ulonglong2 v = k2[j];
            r0 += (v.x > k0) + (v.y > k0);
            r1 += (v.x > k1) + (v.y > k1);
        }
        bool nt0 = (r0 >= TOPK);
        bool nt1 = (r1 >= TOPK);

        // Ballot scan: slots 0-7 cover c = t (0..255), 8-15 cover c = t+256.
        unsigned bal0 = __ballot_sync(0xFFFFFFFFu, nt0);
        unsigned bal1 = __ballot_sync(0xFFFFFFFFu, nt1);
        int warp = t >> 5, lane = t & 31;
        if (lane == 0) { ballots[warp] = bal0; ballots[8 + warp] = bal1; }
        __syncthreads();

        int pre0 = 0, pre1 = 0;
        #pragma unroll
        for (int w = 0; w < 16; ++w) {
            unsigned m = ballots[w];
            if (w < warp)     pre0 += __popc(m);
            if (w < 8 + warp) pre1 += __popc(m);
        }
        unsigned lt = (1u << lane) - 1u;
        int p0 = pre0 + __popc(bal0 & lt);
        int p1 = pre1 + __popc(bal1 & lt);

        if (nt0) g_nt[a][p0] = t;
        if (nt1) g_nt[a][p1] = t + 256;
        g_tp[a][t]       = nt0 ? p0 : -1;
        g_tp[a][t + 256] = nt1 ? p1 : -1;

        __syncthreads();
        if (t == 0) {
            __threadfence();               // publish tables before flag
            atomicAdd(&g_ready, 1);
        }
    }

    // ─── Phase 2: source-stationary copy ───
    // Load address is map-independent: issue loads FIRST so the fetch
    // overlaps the map computation / flag spin.
    unsigned c  = row & (C - 1);
    unsigned ab = row >> 9;
    unsigned a  = ab >> 3;                 // source array
    unsigned b  = ab & (B - 1);

    const char* __restrict__ srcb = (const char*)(a ? x2 : x1);
    // Row = 16 KiB = 512 x 32B chunks; thread handles chunks t and t+256.
    unsigned rowoff = (((b << 9) + c) << 14);        // byte offset of row
    U64x4 u0 = ld32_evict_last(srcb + rowoff + ((unsigned)t << 5));
    U64x4 u1 = ld32_evict_last(srcb + rowoff + (((unsigned)t + 256u) << 5));

    // Wait for both tables (loads are in flight meanwhile).
    if (t == 0) {
        while (*(volatile int*)&g_ready != 2) __nanosleep(64);
        __threadfence();                   // acquire
    }
    __syncthreads();

    // Destination: x_a[:,c,:] -> y_a[:,c,:] if c is top in bn_a,
    // else -> y_{a^1}[:, nt_{a^1}[pos_a(c)], :] (order-aligned exchange).
    int tp = g_tp[a][c];
    unsigned dw, dc;
    if (tp < 0) { dw = a;      dc = c; }
    else        { dw = a ^ 1u; dc = (unsigned)g_nt[a ^ 1u][tp]; }
    unsigned drow = (((dw << 3) + b) << 9) + dc;
    // float4 index of destination row base:
    unsigned d4 = (drow << 10) + ((unsigned)t << 1);

    // Streaming stores (evict-first): out is write-once; don't displace inputs.
    __stcs(out + d4,           f4_lo(u0));
    __stcs(out + d4 + 1,       f4_hi(u0));
    __stcs(out + d4 + 512,     f4_lo(u1));
    __stcs(out + d4 + 513,     f4_hi(u1));

    // ─── Reset handshake for the next graph replay (last block only) ───
    if (t == 0) {
        int d = atomicAdd(&g_done, 1);
        if (d == (int)gridDim.x - 1) {
            g_done = 0;
            g_ready = 0;
        }
    }
}

extern "C" void kernel_launch(void* const* d_in, const int* in_sizes, int n_in,
                              void* d_out, int out_size) {
    const float* x1  = (const float*)d_in[0];
    const float* x2  = (const float*)d_in[1];
    const float* bn1 = (const float*)d_in[2];
    const float* bn2 = (const float*)d_in[3];

    const unsigned rows = 2u * B * C;      // 8192 input channel rows
    exchange_fused_kernel<<<rows, 256>>>((const float4*)x1,
                                         (const float4*)x2,
                                         (float4*)d_out,
                                         bn1, bn2);
}

// round 10
// speedup vs baseline: 1.0234x; 1.0234x over previous
#include <cuda_runtime.h>

static constexpr int C = 512;
static constexpr int B = 8;
static constexpr int TOPK = 256;          // C * (1 - EXCHANGE_RATIO)
static constexpr unsigned ROWS = 8192;    // 2 * B * C input channel rows
static constexpr unsigned GRID = 888;     // 148 SMs x 6 blocks: single wave

// Per-array tables (written by the two map blocks):
//   g_tp[a][c] = -1 if channel c is in top-k of |bn_a|, else its position in
//                the ascending-index list of non-top channels (0..255).
//   g_nt[a][k] = k-th non-top channel of array a (ascending index order).
__device__ int g_tp[2][C];
__device__ int g_nt[2][TOPK];
// Handshake state (zero-initialized; reset by the last block each run).
__device__ int g_ready;
__device__ int g_done;

__global__ void __launch_bounds__(256, 6)
exchange_fused_kernel(const float4* __restrict__ x1,
                      const float4* __restrict__ x2,
                      float4* __restrict__ out,
                      const float* __restrict__ bn1,
                      const float* __restrict__ bn2) {
    unsigned bid = blockIdx.x;
    int t = threadIdx.x;

    // ─── Issue first row's loads immediately (map-independent address) ───
    unsigned r = bid;
    {
        // row r = a*4096 + b*512 + c; source row within array = r & 4095.
    }
    const float4* __restrict__ src0 = (r >> 12) ? x2 : x1;
    unsigned s4 = ((r & 4095u) << 10) + (unsigned)t;
    float4 A0 = __ldcs(src0 + s4);
    float4 A1 = __ldcs(src0 + s4 + 256);
    float4 A2 = __ldcs(src0 + s4 + 512);
    float4 A3 = __ldcs(src0 + s4 + 768);

    // ─── Map phase: blocks 886/887 (9-row class) build tables for bn1/bn2 ───
    if (bid >= GRID - 2) {
        __shared__ unsigned long long key[C];
        __shared__ unsigned ballots[16];

        int a = (int)(bid - (GRID - 2));   // 0 -> bn1, 1 -> bn2
        const float* bn = a ? bn2 : bn1;

        // Non-negative floats order like their bit patterns.
        // key = (bits << 10) | (1023 - c): equal values -> smaller index
        // ranks higher, matching jax.lax.top_k tie semantics.
        {
            unsigned b0 = __float_as_uint(fabsf(bn[t]));
            unsigned b1 = __float_as_uint(fabsf(bn[t + 256]));
            key[t]       = ((unsigned long long)b0 << 10) | (unsigned)(1023 - t);
            key[t + 256] = ((unsigned long long)b1 << 10) | (unsigned)(1023 - (t + 256));
        }
        __syncthreads();

        // Each thread ranks two channels; one LDS.128/iter serves both.
        unsigned long long k0 = key[t], k1 = key[t + 256];
        int r0 = 0, r1 = 0;
        const ulonglong2* k2 = (const ulonglong2*)key;
        #pragma unroll 8
        for (int j = 0; j < C / 2; ++j) {
            ulonglong2 v = k2[j];
            r0 += (v.x > k0) + (v.y > k0);
            r1 += (v.x > k1) + (v.y > k1);
        }
        bool nt0 = (r0 >= TOPK);
        bool nt1 = (r1 >= TOPK);

        // Ballot scan: slots 0-7 cover c = t (0..255), 8-15 cover c = t+256.
        unsigned bal0 = __ballot_sync(0xFFFFFFFFu, nt0);
        unsigned bal1 = __ballot_sync(0xFFFFFFFFu, nt1);
        int warp = t >> 5, lane = t & 31;
        if (lane == 0) { ballots[warp] = bal0; ballots[8 + warp] = bal1; }
        __syncthreads();

        int pre0 = 0, pre1 = 0;
        #pragma unroll
        for (int w = 0; w < 16; ++w) {
            unsigned m = ballots[w];
            if (w < warp)     pre0 += __popc(m);
            if (w < 8 + warp) pre1 += __popc(m);
        }
        unsigned lt = (1u << lane) - 1u;
        int p0 = pre0 + __popc(bal0 & lt);
        int p1 = pre1 + __popc(bal1 & lt);

        if (nt0) g_nt[a][p0] = t;
        if (nt1) g_nt[a][p1] = t + 256;
        g_tp[a][t]       = nt0 ? p0 : -1;
        g_tp[a][t + 256] = nt1 ? p1 : -1;

        __syncthreads();
        if (t == 0) {
            __threadfence();               // publish tables before flag
            atomicAdd(&g_ready, 1);
        }
    }

    // ─── Wait for both tables (first-row loads in flight meanwhile).
    // All 888 blocks are co-resident (6/SM cap), so this cannot deadlock. ───
    if (t == 0) {
        while (*(volatile int*)&g_ready != 2) __nanosleep(64);
        __threadfence();                   // acquire
    }
    __syncthreads();

    // ─── Persistent copy loop over rows bid, bid+888, ... with next-row
    // prefetch: ~128 B/thread continuously in flight. ───
    for (;;) {
        unsigned a = r >> 12;
        unsigned c = r & 511u;
        unsigned b = (r >> 9) & 7u;

        // Destination: x_a[:,c,:] -> y_a[:,c,:] if c is top in bn_a,
        // else -> y_{a^1}[:, nt_{a^1}[pos_a(c)], :] (order-aligned exchange).
        int tp = g_tp[a][c];
        unsigned dw, dc;
        if (tp < 0) { dw = a;      dc = c; }
        else        { dw = a ^ 1u; dc = (unsigned)g_nt[a ^ 1u][tp]; }
        unsigned d4 = (((((dw << 3) + b) << 9) + dc) << 10) + (unsigned)t;

        // Prefetch next row before storing the current one.
        unsigned rn = r + GRID;
        bool more = (rn < ROWS);
        float4 B0, B1, B2, B3;
        if (more) {
            const float4* __restrict__ sn = (rn >> 12) ? x2 : x1;
            unsigned n4 = ((rn & 4095u) << 10) + (unsigned)t;
            B0 = __ldcs(sn + n4);
            B1 = __ldcs(sn + n4 + 256);
            B2 = __ldcs(sn + n4 + 512);
            B3 = __ldcs(sn + n4 + 768);
        }

        // Streaming stores (evict-first): out is write-once dead data.
        __stcs(out + d4,       A0);
        __stcs(out + d4 + 256, A1);
        __stcs(out + d4 + 512, A2);
        __stcs(out + d4 + 768, A3);

        if (!more) break;
        A0 = B0; A1 = B1; A2 = B2; A3 = B3;
        r = rn;
    }

    // ─── Reset handshake for the next graph replay (last block only) ───
    if (t == 0) {
        int d = atomicAdd(&g_done, 1);
        if (d == (int)GRID - 1) {
            g_done = 0;
            g_ready = 0;
        }
    }
}

extern "C" void kernel_launch(void* const* d_in, const int* in_sizes, int n_in,
                              void* d_out, int out_size) {
    const float* x1  = (const float*)d_in[0];
    const float* x2  = (const float*)d_in[1];
    const float* bn1 = (const float*)d_in[2];
    const float* bn2 = (const float*)d_in[3];

    exchange_fused_kernel<<<GRID, 256>>>((const float4*)x1,
                                         (const float4*)x2,
                                         (float4*)d_out,
                                         bn1, bn2);
}

// round 11
// speedup vs baseline: 1.1882x; 1.1610x over previous
#include <cuda_runtime.h>

static constexpr int C = 512;
static constexpr int B = 8;
static constexpr int TOPK = 256;            // C * (1 - EXCHANGE_RATIO)
static constexpr unsigned ROWS = 8192;      // 2 * B * C input channel rows
static constexpr int NRANK = 32;            // map blocks (16 per array)

// g_mask[a][w]: bit (c&31) of word w=c>>5 set  <=>  channel c is NON-top in
// |bn_a|. Fully rewritten every run (plain stores, one word per rank block).
__device__ unsigned g_mask[2][16];
// Handshake (zero-initialized; reset by the last block each run).
__device__ int g_ready;
__device__ int g_done;

__global__ void __launch_bounds__(256)
exchange_fused_kernel(const float4* __restrict__ x1,
                      const float4* __restrict__ x2,
                      float4* __restrict__ out,
                      const float* __restrict__ bn1,
                      const float* __restrict__ bn2) {
    unsigned row = blockIdx.x;              // INPUT row: a*4096 + b*512 + c
    int t = threadIdx.x;

    // ─── Issue this row's loads FIRST (address is map-independent), so the
    // DRAM fetch overlaps the map phase / flag spin. ───
    unsigned c  = row & 511u;
    unsigned a  = row >> 12;                // source array
    unsigned b  = (row >> 9) & 7u;
    const float4* __restrict__ src = a ? x2 : x1;
    unsigned s4 = ((row & 4095u) << 10) + (unsigned)t;
    float4 v0 = __ldcs(src + s4);
    float4 v1 = __ldcs(src + s4 + 256);
    float4 v2 = __ldcs(src + s4 + 512);
    float4 v3 = __ldcs(src + s4 + 768);

    // ─── Map phase, distributed: blocks 0..31 each rank 32 channels and
    // publish one mask word. Block (aa*16 + j) covers channels [j*32, j*32+32)
    // of bn_{aa}. 8 lanes per channel, interleaved LDS (conflict-free). ───
    if (row < NRANK) {
        __shared__ unsigned long long key[C];
        __shared__ unsigned wsh;

        int aa = (int)(row >> 4);
        int j  = (int)(row & 15u);
        const float* bn = aa ? bn2 : bn1;

        // Non-negative floats order like their bit patterns.
        // key = (bits << 10) | (1023 - c): equal values -> smaller index
        // ranks higher, matching jax.lax.top_k tie semantics.
        {
            unsigned b0 = __float_as_uint(fabsf(bn[t]));
            unsigned b1 = __float_as_uint(fabsf(bn[t + 256]));
            key[t]       = ((unsigned long long)b0 << 10) | (unsigned)(1023 - t);
            key[t + 256] = ((unsigned long long)b1 << 10) | (unsigned)(1023 - (t + 256));
        }
        if (t == 0) wsh = 0u;
        __syncthreads();

        // Thread t: channel ch = j*32 + (t>>3); lane-part (t&7) covers keys
        // j2 = part + 8*i (i<32) as ulonglong2 -> lanes 0..7 hit 8 consecutive
        // 16B words (no bank conflicts), lanes 8.. broadcast.
        int ch   = (j << 5) + (t >> 3);
        int part = t & 7;
        unsigned long long k = key[ch];
        int r = 0;
        const ulonglong2* k2 = (const ulonglong2*)key;
        #pragma unroll 8
        for (int i = 0; i < 32; ++i) {
            ulonglong2 v = k2[part + (i << 3)];
            r += (v.x > k) + (v.y > k);
        }
        // Sum the 8 partial counts within each 8-lane group.
        r += __shfl_down_sync(0xFFFFFFFFu, r, 4, 8);
        r += __shfl_down_sync(0xFFFFFFFFu, r, 2, 8);
        r += __shfl_down_sync(0xFFFFFFFFu, r, 1, 8);
        if (part == 0 && r >= TOPK)
            atomicOr(&wsh, 1u << (ch & 31));
        __syncthreads();

        if (t == 0) {
            g_mask[aa][j] = wsh;            // plain store: block owns this word
            __threadfence();                // publish before flag
            atomicAdd(&g_ready, 1);
        }
    }

    // ─── Wait for all 32 mask words (row loads in flight meanwhile). ───
    if (t == 0) {
        while (*(volatile int*)&g_ready != NRANK) __nanosleep(32);
        __threadfence();                    // acquire
    }
    __syncthreads();

    // ─── Destination from masks (uniform per block, ~30 instrs, L2-hot):
    // x_a[:,c,:] -> y_a[:,c,:] if c is top in bn_a, else
    // -> y_{a^1}[:, (p-th nontop channel of a^1), :] where p = position of c
    // among a's nontop channels (ascending index). ───
    unsigned cw = c >> 5, cb = c & 31u;
    unsigned mw = g_mask[a][cw];
    unsigned dw, dc;
    if (!((mw >> cb) & 1u)) {
        dw = a; dc = c;
    } else {
        int p = __popc(mw & ((1u << cb) - 1u));
        for (unsigned w = 0; w < cw; ++w) p += __popc(g_mask[a][w]);
        dw = a ^ 1u;
        int rem = p;
        dc = 0;
        #pragma unroll
        for (int w = 0; w < 16; ++w) {
            unsigned m = g_mask[dw][w];
            int pc = __popc(m);
            if (rem < pc) { dc = ((unsigned)w << 5) + __fns(m, 0, rem + 1); break; }
            rem -= pc;
        }
    }
    unsigned d4 = (((((dw << 3) + b) << 9) + dc) << 10) + (unsigned)t;

    // Streaming stores (evict-first): out is write-once dead data.
    __stcs(out + d4,       v0);
    __stcs(out + d4 + 256, v1);
    __stcs(out + d4 + 512, v2);
    __stcs(out + d4 + 768, v3);

    // ─── Reset handshake for the next graph replay (last block only). ───
    if (t == 0) {
        int d = atomicAdd(&g_done, 1);
        if (d == (int)ROWS - 1) {
            g_done = 0;
            g_ready = 0;
        }
    }
}

extern "C" void kernel_launch(void* const* d_in, const int* in_sizes, int n_in,
                              void* d_out, int out_size) {
    const float* x1  = (const float*)d_in[0];
    const float* x2  = (const float*)d_in[1];
    const float* bn1 = (const float*)d_in[2];
    const float* bn2 = (const float*)d_in[3];

    exchange_fused_kernel<<<ROWS, 256>>>((const float4*)x1,
                                         (const float4*)x2,
                                         (float4*)d_out,
                                         bn1, bn2);
}